// round 16
// baseline (speedup 1.0000x reference)
#include <cuda_runtime.h>
#include <math.h>

#define Bq   2
#define Nn   2048
#define Dd   256
#define Hh   4
#define DHd  64
#define Jj   32
#define FFf  4
#define Mm   16
#define HID  274
#define HP   288            // padded hidden dim (cols 274..287 zero)
#define W2S  292            // sW2t row stride (floats)
#define QKVC (3*Hh*DHd)     // 768
#define NODES (Bq*Nn)       // 4096
#define EDGE_GRID 296       // 2 CTAs/SM x 148 SMs

// ---------------- scratch ----------------
__device__ float g_qkv [Bq*Nn*QKVC];
__device__ float g_q1  [Bq*Nn*Hh*HP];
__device__ float g_k1  [Bq*Nn*Hh*HP];
__device__ float g_outh[Bq*Nn*Dd];

// ---------------- gemm8x8: 128x128x32 double-buffered SGEMM, 8x8 micro ----------------
#define GBM 128
#define GBN 128
#define GBK 32
#define GST (GBK*132)

__global__ void __launch_bounds__(256, 2) gemm8x8(
    const float* __restrict__ A, const float* __restrict__ B,
    const float* __restrict__ bias, float* __restrict__ C,
    int M, int N, int K, int lda, int ldb, int ldc)
{
    extern __shared__ float gsm[];
    float* As = gsm;
    float* Bs = gsm + 2*GST;
    int tid = threadIdx.x;
    int tx = tid & 15, ty = tid >> 4;
    int rowBase = blockIdx.y * GBM;
    int colBase = blockIdx.x * GBN;

    int ar = tid >> 1;
    int ah = tid & 1;
    int bk = tid >> 3;
    int bq = tid & 7;

    {
        const float* Ap = A + (long)(rowBase + ar) * lda + ah*16;
        #pragma unroll
        for (int q = 0; q < 4; q++) {
            float4 v = *(const float4*)(Ap + q*4);
            float* dst = As + (ah*16 + q*4)*132 + ar;
            dst[0] = v.x; dst[132] = v.y; dst[264] = v.z; dst[396] = v.w;
        }
        const float* Bp = B + (long)bk * ldb + colBase + bq*16;
        #pragma unroll
        for (int q = 0; q < 4; q++)
            *(float4*)(Bs + bk*132 + bq*16 + q*4) = *(const float4*)(Bp + q*4);
    }
    __syncthreads();

    float acc[8][8] = {};
    float4 pa[4], pb[4];
    int nkb = K / GBK;
    for (int kb = 0; kb < nkb; kb++) {
        int cur = kb & 1;
        if (kb + 1 < nkb) {
            const float* Ap = A + (long)(rowBase + ar)*lda + (kb+1)*GBK + ah*16;
            #pragma unroll
            for (int q = 0; q < 4; q++) pa[q] = *(const float4*)(Ap + q*4);
            const float* Bp = B + (long)((kb+1)*GBK + bk)*ldb + colBase + bq*16;
            #pragma unroll
            for (int q = 0; q < 4; q++) pb[q] = *(const float4*)(Bp + q*4);
        }
        const float* Ac = As + cur*GST;
        const float* Bc = Bs + cur*GST;
        #pragma unroll
        for (int kk = 0; kk < GBK; kk++) {
            float4 a0 = *(const float4*)(Ac + kk*132 + ty*8);
            float4 a1 = *(const float4*)(Ac + kk*132 + ty*8 + 4);
            float4 b0 = *(const float4*)(Bc + kk*132 + tx*8);
            float4 b1 = *(const float4*)(Bc + kk*132 + tx*8 + 4);
            float av0=a0.x, av1=a0.y, av2=a0.z, av3=a0.w;
            float av4=a1.x, av5=a1.y, av6=a1.z, av7=a1.w;
            float bv0=b0.x, bv1=b0.y, bv2=b0.z, bv3=b0.w;
            float bv4=b1.x, bv5=b1.y, bv6=b1.z, bv7=b1.w;
            #define ROW(r, avr) \
                acc[r][0]+=avr*bv0; acc[r][1]+=avr*bv1; acc[r][2]+=avr*bv2; acc[r][3]+=avr*bv3; \
                acc[r][4]+=avr*bv4; acc[r][5]+=avr*bv5; acc[r][6]+=avr*bv6; acc[r][7]+=avr*bv7;
            ROW(0, av0) ROW(1, av1) ROW(2, av2) ROW(3, av3)
            ROW(4, av4) ROW(5, av5) ROW(6, av6) ROW(7, av7)
            #undef ROW
        }
        if (kb + 1 < nkb) {
            int nxt = cur ^ 1;
            #pragma unroll
            for (int q = 0; q < 4; q++) {
                float* dst = As + nxt*GST + (ah*16 + q*4)*132 + ar;
                dst[0] = pa[q].x; dst[132] = pa[q].y; dst[264] = pa[q].z; dst[396] = pa[q].w;
            }
            #pragma unroll
            for (int q = 0; q < 4; q++)
                *(float4*)(Bs + nxt*GST + bk*132 + bq*16 + q*4) = pb[q];
        }
        __syncthreads();
    }

    #pragma unroll
    for (int r = 0; r < 8; r++) {
        long row = rowBase + ty*8 + r;
        float* Crow = C + row*ldc + colBase + tx*8;
        #pragma unroll
        for (int c2 = 0; c2 < 2; c2++) {
            float4 v;
            v.x = acc[r][c2*4+0]; v.y = acc[r][c2*4+1];
            v.z = acc[r][c2*4+2]; v.w = acc[r][c2*4+3];
            if (bias) {
                const float* bp = bias + colBase + tx*8 + c2*4;
                v.x += bp[0]; v.y += bp[1]; v.z += bp[2]; v.w += bp[3];
            }
            *(float4*)(Crow + c2*4) = v;
        }
    }
}

// ---------------- qk1 (256 threads): 32 nodes/block, 2 chunks ----------------
__global__ void __launch_bounds__(256,1) qk1_kernel(
    const float* __restrict__ qkv, const float* __restrict__ w_e1,
    const float* __restrict__ b_e1,
    float* __restrict__ q1, float* __restrict__ k1)
{
    extern __shared__ float sm[];
    float* sWq = sm;
    float* sWk = sWq + 64*HP;
    float* sAq = sWk + 64*HP;
    float* sAk = sAq + 16*256;
    int tid = threadIdx.x;

    for (int i = tid; i < 64*HP; i += 256) {
        int r = i / HP, o = i - r*HP;
        sWq[i] = (o < HID) ? w_e1[r*HID + o] : 0.f;
        sWk[i] = (o < HID) ? w_e1[(64 + r)*HID + o] : 0.f;
    }

    int ty = tid >> 4, tx = tid & 15;

    for (int chunk = 0; chunk < 2; chunk++) {
        int node0 = blockIdx.x * 32 + chunk * 16;
        __syncthreads();
        for (int i = tid; i < 1024; i += 256) {
            int t = i >> 6, cq = i & 63;
            *(float4*)&sAq[t*256 + cq*4] =
                *(const float4*)&qkv[(long)(node0 + t)*QKVC + cq*4];
            *(float4*)&sAk[t*256 + cq*4] =
                *(const float4*)&qkv[(long)(node0 + t)*QKVC + 256 + cq*4];
        }
        __syncthreads();

        for (int pass = 0; pass < 2; pass++) {
            const float* A = pass ? sAk : sAq;
            const float* W = pass ? sWk : sWq;
            float* Cg = pass ? k1 : q1;
            float acc[4][18];
            #pragma unroll
            for (int r = 0; r < 4; r++)
                #pragma unroll
                for (int c = 0; c < 18; c++) acc[r][c] = 0.f;
            #pragma unroll 4
            for (int i = 0; i < 64; i++) {
                float a[4];
                #pragma unroll
                for (int r = 0; r < 4; r++) a[r] = A[ty*256 + r*64 + i];
                #pragma unroll
                for (int c = 0; c < 18; c++) {
                    float w = W[i*HP + tx + 16*c];
                    #pragma unroll
                    for (int r = 0; r < 4; r++) acc[r][c] += a[r] * w;
                }
            }
            #pragma unroll
            for (int r = 0; r < 4; r++) {
                long grow = (long)(node0 + ty)*4 + r;
                #pragma unroll
                for (int c = 0; c < 18; c++) {
                    int o = tx + 16*c;
                    float bz = (pass == 0 && o < HID) ? b_e1[o] : 0.f;
                    Cg[grow*HP + o] = acc[r][c] + bz;
                }
            }
        }
    }
}

// ---------------- edge_fused: edge MLP + softmax + v-gather + coors, persistent ----------------
__global__ void __launch_bounds__(256, 2) edge_fused(
    const float* __restrict__ q1, const float* __restrict__ k1,
    const float* __restrict__ qkv,
    const float* __restrict__ coors, const int* __restrict__ nbhd,
    const float* __restrict__ basis,
    const float* __restrict__ w_e1,
    const float* __restrict__ w_e2, const float* __restrict__ b_e2,
    const float* __restrict__ w_a1, const float* __restrict__ b_a1,
    const float* __restrict__ w_a2, const float* __restrict__ b_a2,
    const float* __restrict__ w_c1, const float* __restrict__ b_c1,
    const float* __restrict__ w_c2, const float* __restrict__ b_c2,
    float* __restrict__ outh, float* __restrict__ coors_out)
{
    extern __shared__ float sm[];
    float* sWr  = sm;               // [9][HP]
    float* sW2t = sWr + 9*HP;       // [16][W2S]
    float* sA1  = sW2t + 16*W2S;    // [16][64]
    float* sC1  = sA1 + 1024;       // [16][64]
    float* sBa  = sC1 + 1024;       // [64]
    float* sBc  = sBa + 64;         // [64]
    float* sA2  = sBc + 64;         // [64]
    float* sC2  = sA2 + 64;         // [64]
    float* sB2  = sC2 + 64;         // [16]
    float* sScal= sB2 + 16;         // [4]
    float* sQ1  = sScal + 4;        // [4][HP] (per node)
    float* sSim = sQ1 + 4*HP;       // [4][32]
    float* sCw  = sSim + 128;       // [4][32]
    int*   sIdx = (int*)(sCw + 128);// [32]

    int tid = threadIdx.x;

    // ---- one-time weight staging ----
    for (int i = tid; i < 9*HP; i += 256) {
        int f = i / HP, o = i - f*HP;
        sWr[i] = (o < HID) ? w_e1[(128 + f)*HID + o] : 0.f;
    }
    for (int i = tid; i < 16*(W2S - HID); i += 256) {
        int t = i / (W2S - HID), o = HID + i % (W2S - HID);
        sW2t[t*W2S + o] = 0.f;
    }
    for (int i = tid; i < HID*4; i += 256) {
        int irow = i >> 2, tq = i & 3;
        float4 v = *(const float4*)&w_e2[irow*16 + tq*4];
        sW2t[(tq*4+0)*W2S + irow] = v.x;
        sW2t[(tq*4+1)*W2S + irow] = v.y;
        sW2t[(tq*4+2)*W2S + irow] = v.z;
        sW2t[(tq*4+3)*W2S + irow] = v.w;
    }
    if (tid < 256) {
        ((float4*)sA1)[tid] = ((const float4*)w_a1)[tid];
        ((float4*)sC1)[tid] = ((const float4*)w_c1)[tid];
    }
    if (tid < 16) {
        ((float4*)sBa)[tid] = ((const float4*)b_a1)[tid];
        ((float4*)sBc)[tid] = ((const float4*)b_c1)[tid];
        ((float4*)sA2)[tid] = ((const float4*)w_a2)[tid];
        ((float4*)sC2)[tid] = ((const float4*)w_c2)[tid];
    }
    if (tid < 16) sB2[tid] = b_e2[tid];
    if (tid == 0) { sScal[0] = b_a2[0]; sScal[1] = b_c2[0]; }

    int w = tid >> 5, lane = tid & 31;
    int qq = lane >> 3, s = lane & 7;
    int j = w*4 + qq;
    int rq = tid >> 3;      // branch-phase j
    int uo = tid & 7;       // branch-phase u-octet

    // ---- persistent loop over nodes ----
    for (int bn = blockIdx.x; bn < NODES; bn += EDGE_GRID) {
        int bB = bn >> 11;

        __syncthreads();
        for (int i = tid; i < (4*HP)/4; i += 256)
            ((float4*)sQ1)[i] = ((const float4*)(q1 + (long)bn*4*HP))[i];
        if (tid < 32) sIdx[tid] = nbhd[bn*Jj + tid];
        __syncthreads();

        int idx = sIdx[j];
        long krow = ((long)(bB*Nn + idx)*4) * HP;

        float dx = coors[bn*3+0] - coors[(bB*Nn+idx)*3+0];
        float dy = coors[bn*3+1] - coors[(bB*Nn+idx)*3+1];
        float dz = coors[bn*3+2] - coors[(bB*Nn+idx)*3+2];
        float x = dx*dx + dy*dy + dz*dz;
        float xs = x / (float)(1 << (s & 3));
        float sv = sinf(xs), cv = cosf(xs);
        float myre = (s < 4) ? sv : cv;
        float re[9];
        #pragma unroll
        for (int f = 0; f < 8; f++) re[f] = __shfl_sync(0xffffffffu, myre, f, 8);
        re[8] = x;

        float acc[4][16];
        #pragma unroll
        for (int h = 0; h < 4; h++)
            #pragma unroll
            for (int t = 0; t < 16; t++) acc[h][t] = 0.f;

        #pragma unroll 3
        for (int r = 0; r < 9; r++) {
            int i0 = (s + 8*r) * 4;
            float4 k4[4];
            #pragma unroll
            for (int h = 0; h < 4; h++)
                k4[h] = *(const float4*)&k1[krow + h*HP + i0];
            float4 r1v = make_float4(0.f, 0.f, 0.f, 0.f);
            #pragma unroll
            for (int f = 0; f < 9; f++) {
                float4 wv = *(float4*)&sWr[f*HP + i0];
                r1v.x += re[f]*wv.x; r1v.y += re[f]*wv.y;
                r1v.z += re[f]*wv.z; r1v.w += re[f]*wv.w;
            }
            float4 hv[4];
            #pragma unroll
            for (int h = 0; h < 4; h++) {
                float4 q4 = *(float4*)&sQ1[h*HP + i0];
                hv[h].x = fmaxf(q4.x + k4[h].x + r1v.x, 0.f);
                hv[h].y = fmaxf(q4.y + k4[h].y + r1v.y, 0.f);
                hv[h].z = fmaxf(q4.z + k4[h].z + r1v.z, 0.f);
                hv[h].w = fmaxf(q4.w + k4[h].w + r1v.w, 0.f);
            }
            #pragma unroll
            for (int t = 0; t < 16; t++) {
                float4 wv = *(float4*)&sW2t[t*W2S + i0];
                #pragma unroll
                for (int h = 0; h < 4; h++)
                    acc[h][t] += hv[h].x*wv.x + hv[h].y*wv.y
                               + hv[h].z*wv.z + hv[h].w*wv.w;
            }
        }

        // butterfly reduce over 8-lane group
        #pragma unroll
        for (int h = 0; h < 4; h++)
            #pragma unroll
            for (int t = 0; t < 16; t++) {
                float v = acc[h][t];
                v += __shfl_xor_sync(0xffffffffu, v, 1);
                v += __shfl_xor_sync(0xffffffffu, v, 2);
                v += __shfl_xor_sync(0xffffffffu, v, 4);
                acc[h][t] = v;
            }

        // branch handoff via shfl
        float mvr[4][16];
        #pragma unroll
        for (int rr = 0; rr < 4; rr++)
            #pragma unroll
            for (int t = 0; t < 16; t++) {
                float v = __shfl_sync(0xffffffffu, acc[rr][t], (lane & 24) | rr, 32);
                mvr[rr][t] = fmaxf(v + sB2[t], 0.f);
            }

        // blocked branch GEMM -> sim/cw into smem
        #pragma unroll
        for (int br = 0; br < 2; br++) {
            const float* w1 = br ? sC1 : sA1;
            const float* w2 = br ? sC2 : sA2;
            const float* bb = br ? sBc : sBa;
            float4 bA = *(float4*)&bb[uo*8];
            float4 bBv = *(float4*)&bb[uo*8 + 4];
            float4 hA[4], hB[4];
            #pragma unroll
            for (int r = 0; r < 4; r++) { hA[r] = bA; hB[r] = bBv; }
            #pragma unroll
            for (int t = 0; t < 16; t++) {
                float4 wA = *(float4*)&w1[t*64 + uo*8];
                float4 wB = *(float4*)&w1[t*64 + uo*8 + 4];
                #pragma unroll
                for (int r = 0; r < 4; r++) {
                    float mval = mvr[r][t];
                    hA[r].x += mval*wA.x; hA[r].y += mval*wA.y;
                    hA[r].z += mval*wA.z; hA[r].w += mval*wA.w;
                    hB[r].x += mval*wB.x; hB[r].y += mval*wB.y;
                    hB[r].z += mval*wB.z; hB[r].w += mval*wB.w;
                }
            }
            float4 w2A = *(float4*)&w2[uo*8];
            float4 w2B = *(float4*)&w2[uo*8 + 4];
            float part[4];
            #pragma unroll
            for (int r = 0; r < 4; r++) {
                part[r] = fmaxf(hA[r].x,0.f)*w2A.x + fmaxf(hA[r].y,0.f)*w2A.y
                        + fmaxf(hA[r].z,0.f)*w2A.z + fmaxf(hA[r].w,0.f)*w2A.w
                        + fmaxf(hB[r].x,0.f)*w2B.x + fmaxf(hB[r].y,0.f)*w2B.y
                        + fmaxf(hB[r].z,0.f)*w2B.z + fmaxf(hB[r].w,0.f)*w2B.w;
            }
            #pragma unroll
            for (int r = 0; r < 4; r++) {
                part[r] += __shfl_xor_sync(0xffffffffu, part[r], 1);
                part[r] += __shfl_xor_sync(0xffffffffu, part[r], 2);
                part[r] += __shfl_xor_sync(0xffffffffu, part[r], 4);
            }
            if (uo == 0) {
                float* dst = br ? sCw : sSim;
                float bias2 = sScal[br];
                #pragma unroll
                for (int r = 0; r < 4; r++)
                    dst[r*32 + rq] = part[r] + bias2;
            }
        }
        __syncthreads();

        // ---- fused attend: warps 0-3 = heads (lane = j); warp 4 = coors ----
        if (w < 4) {
            float sval = sSim[w*32 + lane];
            float mx = sval;
            #pragma unroll
            for (int o = 16; o; o >>= 1) mx = fmaxf(mx, __shfl_xor_sync(0xffffffffu, mx, o));
            float e = expf(sval - mx);
            float sum = e;
            #pragma unroll
            for (int o = 16; o; o >>= 1) sum += __shfl_xor_sync(0xffffffffu, sum, o);
            float attn = e / sum;
            int myidx = sIdx[lane];

            float acc0 = 0.f, acc1 = 0.f;
            #pragma unroll
            for (int jj = 0; jj < Jj; jj++) {
                float a = __shfl_sync(0xffffffffu, attn, jj);
                int ij  = __shfl_sync(0xffffffffu, myidx, jj);
                const float* vr = qkv + (long)(bB*Nn + ij)*QKVC + 2*Hh*DHd + w*DHd;
                acc0 += a * vr[lane];
                acc1 += a * vr[lane + 32];
            }
            outh[(long)bn*Dd + w*DHd + lane]      = acc0;
            outh[(long)bn*Dd + w*DHd + lane + 32] = acc1;
        } else if (w == 4) {
            float cwt = sCw[lane] + sCw[32 + lane] + sCw[64 + lane] + sCw[96 + lane];
            int myidx = sIdx[lane];
            const float* brow = basis + ((long)bn*Nn + myidx)*3;
            float cx = cwt*brow[0], cy = cwt*brow[1], cz = cwt*brow[2];
            #pragma unroll
            for (int o = 16; o; o >>= 1) {
                cx += __shfl_xor_sync(0xffffffffu, cx, o);
                cy += __shfl_xor_sync(0xffffffffu, cy, o);
                cz += __shfl_xor_sync(0xffffffffu, cz, o);
            }
            if (lane == 0) {
                coors_out[bn*3+0] = cx;
                coors_out[bn*3+1] = cy;
                coors_out[bn*3+2] = cz;
            }
        }
    }
}

// ---------------- launch ----------------
extern "C" void kernel_launch(void* const* d_in, const int* in_sizes, int n_in,
                              void* d_out, int out_size)
{
    const float* feats  = (const float*)d_in[0];
    const float* coors  = (const float*)d_in[1];
    const float* basis  = (const float*)d_in[2];
    const int*   nbhd   = (const int*)  d_in[3];
    const float* w_qkv  = (const float*)d_in[4];
    const float* w_out  = (const float*)d_in[5];
    const float* b_out  = (const float*)d_in[6];
    const float* w_e1   = (const float*)d_in[7];
    const float* b_e1   = (const float*)d_in[8];
    const float* w_e2   = (const float*)d_in[9];
    const float* b_e2   = (const float*)d_in[10];
    const float* w_a1   = (const float*)d_in[11];
    const float* b_a1   = (const float*)d_in[12];
    const float* w_a2   = (const float*)d_in[13];
    const float* b_a2   = (const float*)d_in[14];
    const float* w_c1   = (const float*)d_in[15];
    const float* b_c1   = (const float*)d_in[16];
    const float* w_c2   = (const float*)d_in[17];
    const float* b_c2   = (const float*)d_in[18];

    float* out       = (float*)d_out;
    float* coors_out = out + (long)Bq*Nn*Dd;

    void* p;
    cudaGetSymbolAddress(&p, g_qkv);  float* qkv  = (float*)p;
    cudaGetSymbolAddress(&p, g_q1);   float* q1   = (float*)p;
    cudaGetSymbolAddress(&p, g_k1);   float* k1   = (float*)p;
    cudaGetSymbolAddress(&p, g_outh); float* outh = (float*)p;

    const int smemG = 4 * GST * 4;
    cudaFuncSetAttribute(gemm8x8, cudaFuncAttributeMaxDynamicSharedMemorySize, smemG);

    // 1) qkv = feats @ w_qkv
    gemm8x8<<<dim3(QKVC/GBN, (Bq*Nn)/GBM), 256, smemG>>>(
        feats, w_qkv, nullptr, qkv, Bq*Nn, QKVC, Dd, Dd, QKVC, QKVC);

    // 2) q1/k1 tables
    const int smemQK = (64*HP*2 + 16*256*2) * 4;
    cudaFuncSetAttribute(qk1_kernel, cudaFuncAttributeMaxDynamicSharedMemorySize, smemQK);
    qk1_kernel<<<NODES/32, 256, smemQK>>>(qkv, w_e1, b_e1, q1, k1);

    // 3) edge_fused (edge MLP + softmax + v-gather + coors)
    const int smemE = (9*HP + 16*W2S + 1024 + 1024 + 64*4 + 16 + 4 + 4*HP + 128 + 128 + 32) * 4;
    cudaFuncSetAttribute(edge_fused, cudaFuncAttributeMaxDynamicSharedMemorySize, smemE);
    edge_fused<<<EDGE_GRID, 256, smemE>>>(q1, k1, qkv, coors, nbhd, basis,
        w_e1, w_e2, b_e2, w_a1, b_a1, w_a2, b_a2, w_c1, b_c1, w_c2, b_c2,
        outh, coors_out);

    // 4) out = outh @ w_out + b_out
    gemm8x8<<<dim3(Dd/GBN, (Bq*Nn)/GBM), 256, smemG>>>(
        outh, w_out, b_out, out, Bq*Nn, Dd, Dd, Dd, Dd, Dd);
}

// round 17
// speedup vs baseline: 1.0668x; 1.0668x over previous
#include <cuda_runtime.h>
#include <math.h>

#define Bq   2
#define Nn   2048
#define Dd   256
#define Hh   4
#define DHd  64
#define Jj   32
#define FFf  4
#define Mm   16
#define HID  274
#define HP   288            // padded hidden dim (cols 274..287 zero)
#define W2S  292            // sW2t row stride (floats)
#define QKVC (3*Hh*DHd)     // 768
#define NODES (Bq*Nn)       // 4096
#define EDGE_GRID 296       // 2 CTAs/SM x 148 SMs

// ---------------- scratch ----------------
__device__ float g_qkv [Bq*Nn*QKVC];
__device__ float g_q1  [Bq*Nn*Hh*HP];
__device__ float g_k1  [Bq*Nn*Hh*HP];
__device__ float g_sim [Bq*Hh*Nn*Jj];
__device__ float g_cw  [Bq*Hh*Nn*Jj];
__device__ float g_outh[Bq*Nn*Dd];

// ---------------- gemm512: 128x128x32 double-buffered SGEMM, 512 thr, 8x4 micro ----------------
#define GBM 128
#define GBN 128
#define GBK 32
#define GST (GBK*132)

__global__ void __launch_bounds__(512, 1) gemm512(
    const float* __restrict__ A, const float* __restrict__ B,
    const float* __restrict__ bias, float* __restrict__ C,
    int M, int N, int K, int lda, int ldb, int ldc)
{
    extern __shared__ float gsm[];
    float* As = gsm;            // [2][GBK][132]
    float* Bs = gsm + 2*GST;    // [2][GBK][132]
    int tid = threadIdx.x;
    int tx = tid & 31, ty = tid >> 5;      // 32 col-groups x 16 row-groups
    int rowBase = blockIdx.y * GBM;
    int colBase = blockIdx.x * GBN;

    int ar = tid >> 2, ak = (tid & 3) * 8;   // A staging: row, k-offset
    int bk = tid >> 4, bc = (tid & 15) * 8;  // B staging: k, col-offset

    // stage 0
    {
        const float* Ap = A + (long)(rowBase + ar) * lda + ak;
        #pragma unroll
        for (int q = 0; q < 2; q++) {
            float4 v = *(const float4*)(Ap + q*4);
            float* dst = As + (ak + q*4)*132 + ar;
            dst[0] = v.x; dst[132] = v.y; dst[264] = v.z; dst[396] = v.w;
        }
        const float* Bp = B + (long)bk * ldb + colBase + bc;
        #pragma unroll
        for (int q = 0; q < 2; q++)
            *(float4*)(Bs + bk*132 + bc + q*4) = *(const float4*)(Bp + q*4);
    }
    __syncthreads();

    float acc[8][4] = {};
    float4 pa[2], pb[2];
    int nkb = K / GBK;
    for (int kb = 0; kb < nkb; kb++) {
        int cur = kb & 1;
        if (kb + 1 < nkb) {
            const float* Ap = A + (long)(rowBase + ar)*lda + (kb+1)*GBK + ak;
            #pragma unroll
            for (int q = 0; q < 2; q++) pa[q] = *(const float4*)(Ap + q*4);
            const float* Bp = B + (long)((kb+1)*GBK + bk)*ldb + colBase + bc;
            #pragma unroll
            for (int q = 0; q < 2; q++) pb[q] = *(const float4*)(Bp + q*4);
        }
        const float* Ac = As + cur*GST;
        const float* Bc = Bs + cur*GST;
        #pragma unroll
        for (int kk = 0; kk < GBK; kk++) {
            float4 a0 = *(const float4*)(Ac + kk*132 + ty*8);
            float4 a1 = *(const float4*)(Ac + kk*132 + ty*8 + 4);
            float4 b0 = *(const float4*)(Bc + kk*132 + tx*4);
            float av[8] = {a0.x, a0.y, a0.z, a0.w, a1.x, a1.y, a1.z, a1.w};
            #pragma unroll
            for (int r = 0; r < 8; r++) {
                acc[r][0] += av[r]*b0.x;
                acc[r][1] += av[r]*b0.y;
                acc[r][2] += av[r]*b0.z;
                acc[r][3] += av[r]*b0.w;
            }
        }
        if (kb + 1 < nkb) {
            int nxt = cur ^ 1;
            #pragma unroll
            for (int q = 0; q < 2; q++) {
                float* dst = As + nxt*GST + (ak + q*4)*132 + ar;
                dst[0] = pa[q].x; dst[132] = pa[q].y; dst[264] = pa[q].z; dst[396] = pa[q].w;
            }
            #pragma unroll
            for (int q = 0; q < 2; q++)
                *(float4*)(Bs + nxt*GST + bk*132 + bc + q*4) = pb[q];
        }
        __syncthreads();
    }

    #pragma unroll
    for (int r = 0; r < 8; r++) {
        long row = rowBase + ty*8 + r;
        float* Crow = C + row*ldc + colBase + tx*4;
        float4 v;
        v.x = acc[r][0]; v.y = acc[r][1]; v.z = acc[r][2]; v.w = acc[r][3];
        if (bias) {
            const float* bp = bias + colBase + tx*4;
            v.x += bp[0]; v.y += bp[1]; v.z += bp[2]; v.w += bp[3];
        }
        *(float4*)Crow = v;
    }
}

// ---------------- qk1 (256 threads): 32 nodes/block, 2 chunks ----------------
__global__ void __launch_bounds__(256,1) qk1_kernel(
    const float* __restrict__ qkv, const float* __restrict__ w_e1,
    const float* __restrict__ b_e1,
    float* __restrict__ q1, float* __restrict__ k1)
{
    extern __shared__ float sm[];
    float* sWq = sm;
    float* sWk = sWq + 64*HP;
    float* sAq = sWk + 64*HP;
    float* sAk = sAq + 16*256;
    int tid = threadIdx.x;

    for (int i = tid; i < 64*HP; i += 256) {
        int r = i / HP, o = i - r*HP;
        sWq[i] = (o < HID) ? w_e1[r*HID + o] : 0.f;
        sWk[i] = (o < HID) ? w_e1[(64 + r)*HID + o] : 0.f;
    }

    int ty = tid >> 4, tx = tid & 15;

    for (int chunk = 0; chunk < 2; chunk++) {
        int node0 = blockIdx.x * 32 + chunk * 16;
        __syncthreads();
        for (int i = tid; i < 1024; i += 256) {
            int t = i >> 6, cq = i & 63;
            *(float4*)&sAq[t*256 + cq*4] =
                *(const float4*)&qkv[(long)(node0 + t)*QKVC + cq*4];
            *(float4*)&sAk[t*256 + cq*4] =
                *(const float4*)&qkv[(long)(node0 + t)*QKVC + 256 + cq*4];
        }
        __syncthreads();

        for (int pass = 0; pass < 2; pass++) {
            const float* A = pass ? sAk : sAq;
            const float* W = pass ? sWk : sWq;
            float* Cg = pass ? k1 : q1;
            float acc[4][18];
            #pragma unroll
            for (int r = 0; r < 4; r++)
                #pragma unroll
                for (int c = 0; c < 18; c++) acc[r][c] = 0.f;
            #pragma unroll 4
            for (int i = 0; i < 64; i++) {
                float a[4];
                #pragma unroll
                for (int r = 0; r < 4; r++) a[r] = A[ty*256 + r*64 + i];
                #pragma unroll
                for (int c = 0; c < 18; c++) {
                    float w = W[i*HP + tx + 16*c];
                    #pragma unroll
                    for (int r = 0; r < 4; r++) acc[r][c] += a[r] * w;
                }
            }
            #pragma unroll
            for (int r = 0; r < 4; r++) {
                long grow = (long)(node0 + ty)*4 + r;
                #pragma unroll
                for (int c = 0; c < 18; c++) {
                    int o = tx + 16*c;
                    float bz = (pass == 0 && o < HID) ? b_e1[o] : 0.f;
                    Cg[grow*HP + o] = acc[r][c] + bz;
                }
            }
        }
    }
}

// ---------------- edge_flat v7: persistent + shfl branch handoff ----------------
__global__ void __launch_bounds__(256, 2) edge_flat(
    const float* __restrict__ q1, const float* __restrict__ k1,
    const float* __restrict__ coors, const int* __restrict__ nbhd,
    const float* __restrict__ w_e1,
    const float* __restrict__ w_e2, const float* __restrict__ b_e2,
    const float* __restrict__ w_a1, const float* __restrict__ b_a1,
    const float* __restrict__ w_a2, const float* __restrict__ b_a2,
    const float* __restrict__ w_c1, const float* __restrict__ b_c1,
    const float* __restrict__ w_c2, const float* __restrict__ b_c2,
    float* __restrict__ simo, float* __restrict__ cwo)
{
    extern __shared__ float sm[];
    float* sWr  = sm;               // [9][HP]
    float* sW2t = sWr + 9*HP;       // [16][W2S]
    float* sA1  = sW2t + 16*W2S;    // [16][64]
    float* sC1  = sA1 + 1024;       // [16][64]
    float* sBa  = sC1 + 1024;       // [64]
    float* sBc  = sBa + 64;         // [64]
    float* sA2  = sBc + 64;         // [64]
    float* sC2  = sA2 + 64;         // [64]
    float* sB2  = sC2 + 64;         // [16]
    float* sScal= sB2 + 16;         // [4]
    float* sQ1  = sScal + 4;        // [4][HP] (per node)
    int*   sIdx = (int*)(sQ1 + 4*HP); // [32]

    int tid = threadIdx.x;

    for (int i = tid; i < 9*HP; i += 256) {
        int f = i / HP, o = i - f*HP;
        sWr[i] = (o < HID) ? w_e1[(128 + f)*HID + o] : 0.f;
    }
    for (int i = tid; i < 16*(W2S - HID); i += 256) {
        int t = i / (W2S - HID), o = HID + i % (W2S - HID);
        sW2t[t*W2S + o] = 0.f;
    }
    for (int i = tid; i < HID*4; i += 256) {
        int irow = i >> 2, tq = i & 3;
        float4 v = *(const float4*)&w_e2[irow*16 + tq*4];
        sW2t[(tq*4+0)*W2S + irow] = v.x;
        sW2t[(tq*4+1)*W2S + irow] = v.y;
        sW2t[(tq*4+2)*W2S + irow] = v.z;
        sW2t[(tq*4+3)*W2S + irow] = v.w;
    }
    if (tid < 256) {
        ((float4*)sA1)[tid] = ((const float4*)w_a1)[tid];
        ((float4*)sC1)[tid] = ((const float4*)w_c1)[tid];
    }
    if (tid < 16) {
        ((float4*)sBa)[tid] = ((const float4*)b_a1)[tid];
        ((float4*)sBc)[tid] = ((const float4*)b_c1)[tid];
        ((float4*)sA2)[tid] = ((const float4*)w_a2)[tid];
        ((float4*)sC2)[tid] = ((const float4*)w_c2)[tid];
    }
    if (tid < 16) sB2[tid] = b_e2[tid];
    if (tid == 0) { sScal[0] = b_a2[0]; sScal[1] = b_c2[0]; }

    int w = tid >> 5, lane = tid & 31;
    int qq = lane >> 3, s = lane & 7;
    int j = w*4 + qq;
    int rq = tid >> 3;
    int uo = tid & 7;

    for (int bn = blockIdx.x; bn < NODES; bn += EDGE_GRID) {
        int bB = bn >> 11;
        int nn = bn & (Nn - 1);

        __syncthreads();
        for (int i = tid; i < (4*HP)/4; i += 256)
            ((float4*)sQ1)[i] = ((const float4*)(q1 + (long)bn*4*HP))[i];
        if (tid < 32) sIdx[tid] = nbhd[bn*Jj + tid];
        __syncthreads();

        int idx = sIdx[j];
        long krow = ((long)(bB*Nn + idx)*4) * HP;

        float dx = coors[bn*3+0] - coors[(bB*Nn+idx)*3+0];
        float dy = coors[bn*3+1] - coors[(bB*Nn+idx)*3+1];
        float dz = coors[bn*3+2] - coors[(bB*Nn+idx)*3+2];
        float x = dx*dx + dy*dy + dz*dz;
        float xs = x / (float)(1 << (s & 3));
        float sv = sinf(xs), cv = cosf(xs);
        float myre = (s < 4) ? sv : cv;
        float re[9];
        #pragma unroll
        for (int f = 0; f < 8; f++) re[f] = __shfl_sync(0xffffffffu, myre, f, 8);
        re[8] = x;

        float acc[4][16];
        #pragma unroll
        for (int h = 0; h < 4; h++)
            #pragma unroll
            for (int t = 0; t < 16; t++) acc[h][t] = 0.f;

        #pragma unroll 3
        for (int r = 0; r < 9; r++) {
            int i0 = (s + 8*r) * 4;
            float4 k4[4];
            #pragma unroll
            for (int h = 0; h < 4; h++)
                k4[h] = *(const float4*)&k1[krow + h*HP + i0];
            float4 r1v = make_float4(0.f, 0.f, 0.f, 0.f);
            #pragma unroll
            for (int f = 0; f < 9; f++) {
                float4 wv = *(float4*)&sWr[f*HP + i0];
                r1v.x += re[f]*wv.x; r1v.y += re[f]*wv.y;
                r1v.z += re[f]*wv.z; r1v.w += re[f]*wv.w;
            }
            float4 hv[4];
            #pragma unroll
            for (int h = 0; h < 4; h++) {
                float4 q4 = *(float4*)&sQ1[h*HP + i0];
                hv[h].x = fmaxf(q4.x + k4[h].x + r1v.x, 0.f);
                hv[h].y = fmaxf(q4.y + k4[h].y + r1v.y, 0.f);
                hv[h].z = fmaxf(q4.z + k4[h].z + r1v.z, 0.f);
                hv[h].w = fmaxf(q4.w + k4[h].w + r1v.w, 0.f);
            }
            #pragma unroll
            for (int t = 0; t < 16; t++) {
                float4 wv = *(float4*)&sW2t[t*W2S + i0];
                #pragma unroll
                for (int h = 0; h < 4; h++)
                    acc[h][t] += hv[h].x*wv.x + hv[h].y*wv.y
                               + hv[h].z*wv.z + hv[h].w*wv.w;
            }
        }

        #pragma unroll
        for (int h = 0; h < 4; h++)
            #pragma unroll
            for (int t = 0; t < 16; t++) {
                float v = acc[h][t];
                v += __shfl_xor_sync(0xffffffffu, v, 1);
                v += __shfl_xor_sync(0xffffffffu, v, 2);
                v += __shfl_xor_sync(0xffffffffu, v, 4);
                acc[h][t] = v;
            }

        float mvr[4][16];
        #pragma unroll
        for (int rr = 0; rr < 4; rr++)
            #pragma unroll
            for (int t = 0; t < 16; t++) {
                float v = __shfl_sync(0xffffffffu, acc[rr][t], (lane & 24) | rr, 32);
                mvr[rr][t] = fmaxf(v + sB2[t], 0.f);
            }

        #pragma unroll
        for (int br = 0; br < 2; br++) {
            const float* w1 = br ? sC1 : sA1;
            const float* w2 = br ? sC2 : sA2;
            const float* bb = br ? sBc : sBa;
            float4 bA = *(float4*)&bb[uo*8];
            float4 bBv = *(float4*)&bb[uo*8 + 4];
            float4 hA[4], hB[4];
            #pragma unroll
            for (int r = 0; r < 4; r++) { hA[r] = bA; hB[r] = bBv; }
            #pragma unroll
            for (int t = 0; t < 16; t++) {
                float4 wA = *(float4*)&w1[t*64 + uo*8];
                float4 wB = *(float4*)&w1[t*64 + uo*8 + 4];
                #pragma unroll
                for (int r = 0; r < 4; r++) {
                    float mval = mvr[r][t];
                    hA[r].x += mval*wA.x; hA[r].y += mval*wA.y;
                    hA[r].z += mval*wA.z; hA[r].w += mval*wA.w;
                    hB[r].x += mval*wB.x; hB[r].y += mval*wB.y;
                    hB[r].z += mval*wB.z; hB[r].w += mval*wB.w;
                }
            }
            float4 w2A = *(float4*)&w2[uo*8];
            float4 w2B = *(float4*)&w2[uo*8 + 4];
            float part[4];
            #pragma unroll
            for (int r = 0; r < 4; r++) {
                part[r] = fmaxf(hA[r].x,0.f)*w2A.x + fmaxf(hA[r].y,0.f)*w2A.y
                        + fmaxf(hA[r].z,0.f)*w2A.z + fmaxf(hA[r].w,0.f)*w2A.w
                        + fmaxf(hB[r].x,0.f)*w2B.x + fmaxf(hB[r].y,0.f)*w2B.y
                        + fmaxf(hB[r].z,0.f)*w2B.z + fmaxf(hB[r].w,0.f)*w2B.w;
            }
            #pragma unroll
            for (int r = 0; r < 4; r++) {
                part[r] += __shfl_xor_sync(0xffffffffu, part[r], 1);
                part[r] += __shfl_xor_sync(0xffffffffu, part[r], 2);
                part[r] += __shfl_xor_sync(0xffffffffu, part[r], 4);
            }
            if (uo == 0) {
                float* dst = br ? cwo : simo;
                float bias2 = sScal[br];
                #pragma unroll
                for (int r = 0; r < 4; r++) {
                    long e = ((long)(bB*Hh + r)*Nn + nn)*Jj + rq;
                    dst[e] = part[r] + bias2;
                }
            }
        }
    }
}

// ---------------- softmax over j, out = attn@v_nb, coors_out ----------------
__global__ void attend_kernel(const float* __restrict__ qkv,
                              const float* __restrict__ simi, const float* __restrict__ cwi,
                              const int* __restrict__ nbhd, const float* __restrict__ basis,
                              float* __restrict__ outh, float* __restrict__ coors_out)
{
    int bn = blockIdx.x;
    int b = bn / Nn, n = bn % Nn;
    int w = threadIdx.x >> 5, lane = threadIdx.x & 31;
    int idx = nbhd[bn*Jj + lane];

    float s = simi[((long)((b*Hh + w)*Nn + n))*Jj + lane];
    float mx = s;
    #pragma unroll
    for (int o = 16; o; o >>= 1) mx = fmaxf(mx, __shfl_xor_sync(0xffffffffu, mx, o));
    float e = expf(s - mx);
    float sum = e;
    #pragma unroll
    for (int o = 16; o; o >>= 1) sum += __shfl_xor_sync(0xffffffffu, sum, o);
    float attn = e / sum;

    float acc0 = 0.f, acc1 = 0.f;
    #pragma unroll
    for (int j = 0; j < Jj; j++) {
        float a = __shfl_sync(0xffffffffu, attn, j);
        int ij  = __shfl_sync(0xffffffffu, idx,  j);
        const float* vr = qkv + (long)(b*Nn + ij)*QKVC + 2*Hh*DHd + w*DHd;
        acc0 += a * vr[lane];
        acc1 += a * vr[lane + 32];
    }
    outh[(long)bn*Dd + w*DHd + lane]      = acc0;
    outh[(long)bn*Dd + w*DHd + lane + 32] = acc1;

    if (w == 0) {
        float cwt = 0.f;
        #pragma unroll
        for (int hh = 0; hh < Hh; hh++)
            cwt += cwi[((long)((b*Hh + hh)*Nn + n))*Jj + lane];
        const float* brow = basis + ((long)(b*Nn + n)*Nn + idx)*3;
        float cx = cwt*brow[0], cy = cwt*brow[1], cz = cwt*brow[2];
        #pragma unroll
        for (int o = 16; o; o >>= 1) {
            cx += __shfl_xor_sync(0xffffffffu, cx, o);
            cy += __shfl_xor_sync(0xffffffffu, cy, o);
            cz += __shfl_xor_sync(0xffffffffu, cz, o);
        }
        if (lane == 0) {
            coors_out[bn*3+0] = cx;
            coors_out[bn*3+1] = cy;
            coors_out[bn*3+2] = cz;
        }
    }
}

// ---------------- launch ----------------
extern "C" void kernel_launch(void* const* d_in, const int* in_sizes, int n_in,
                              void* d_out, int out_size)
{
    const float* feats  = (const float*)d_in[0];
    const float* coors  = (const float*)d_in[1];
    const float* basis  = (const float*)d_in[2];
    const int*   nbhd   = (const int*)  d_in[3];
    const float* w_qkv  = (const float*)d_in[4];
    const float* w_out  = (const float*)d_in[5];
    const float* b_out  = (const float*)d_in[6];
    const float* w_e1   = (const float*)d_in[7];
    const float* b_e1   = (const float*)d_in[8];
    const float* w_e2   = (const float*)d_in[9];
    const float* b_e2   = (const float*)d_in[10];
    const float* w_a1   = (const float*)d_in[11];
    const float* b_a1   = (const float*)d_in[12];
    const float* w_a2   = (const float*)d_in[13];
    const float* b_a2   = (const float*)d_in[14];
    const float* w_c1   = (const float*)d_in[15];
    const float* b_c1   = (const float*)d_in[16];
    const float* w_c2   = (const float*)d_in[17];
    const float* b_c2   = (const float*)d_in[18];

    float* out       = (float*)d_out;
    float* coors_out = out + (long)Bq*Nn*Dd;

    void* p;
    cudaGetSymbolAddress(&p, g_qkv);  float* qkv  = (float*)p;
    cudaGetSymbolAddress(&p, g_q1);   float* q1   = (float*)p;
    cudaGetSymbolAddress(&p, g_k1);   float* k1   = (float*)p;
    cudaGetSymbolAddress(&p, g_sim);  float* simv = (float*)p;
    cudaGetSymbolAddress(&p, g_cw);   float* cwv  = (float*)p;
    cudaGetSymbolAddress(&p, g_outh); float* outh = (float*)p;

    const int smemG = 4 * GST * 4;
    cudaFuncSetAttribute(gemm512, cudaFuncAttributeMaxDynamicSharedMemorySize, smemG);

    // 1) qkv = feats @ w_qkv
    gemm512<<<dim3(QKVC/GBN, (Bq*Nn)/GBM), 512, smemG>>>(
        feats, w_qkv, nullptr, qkv, Bq*Nn, QKVC, Dd, Dd, QKVC, QKVC);

    // 2) q1/k1 tables
    const int smemQK = (64*HP*2 + 16*256*2) * 4;
    cudaFuncSetAttribute(qk1_kernel, cudaFuncAttributeMaxDynamicSharedMemorySize, smemQK);
    qk1_kernel<<<NODES/32, 256, smemQK>>>(qkv, w_e1, b_e1, q1, k1);

    // 3) edge_flat v7 (persistent, shfl branch handoff)
    const int smemE = (9*HP + 16*W2S + 1024 + 1024 + 64*4 + 16 + 4 + 4*HP + 32) * 4;
    cudaFuncSetAttribute(edge_flat, cudaFuncAttributeMaxDynamicSharedMemorySize, smemE);
    edge_flat<<<EDGE_GRID, 256, smemE>>>(q1, k1, coors, nbhd,
        w_e1, w_e2, b_e2, w_a1, b_a1, w_a2, b_a2, w_c1, b_c1, w_c2, b_c2,
        simv, cwv);

    // 4) softmax + v-gather + coors einsum
    attend_kernel<<<Bq*Nn, 128>>>(qkv, simv, cwv, nbhd, basis, outh, coors_out);

    // 5) out = outh @ w_out + b_out
    gemm512<<<dim3(Dd/GBN, (Bq*Nn)/GBM), 512, smemG>>>(
        outh, w_out, b_out, out, Bq*Nn, Dd, Dd, Dd, Dd, Dd);
}